// round 6
// baseline (speedup 1.0000x reference)
#include <cuda_runtime.h>
#include <cuda_bf16.h>

// CenterLoss: loss = mean_b sum_d (features[b,d] - centers[labels[b],d])^2
// B=65536, D=256, C=100000. HBM-bound gather + reduction.
// Stage1: __ldcs streaming on features (protect L2 for center-row reuse),
//         2 rows per warp-iteration (8 independent LDG.128/lane in flight),
//         labels prefetched one pair ahead, partial published with
//         st.release.gpu (no MEMBAR.GPU / CCTL.IVALL L1 flush).
// Stage2: PDL-overlapped, acquire loads of partials.

#define BATCH    65536
#define FEAT_DIM 256
#define GRID1    1184          // 8 CTAs/SM * 148 SMs
#define BLOCK1   256           // 8 warps per CTA
#define NWARPS   ((GRID1 * BLOCK1) >> 5)   // 9472

__device__ __align__(16) float g_partials[GRID1];

__device__ __forceinline__ void store_release_gpu(float* p, float v) {
    asm volatile("st.global.release.gpu.f32 [%0], %1;" :: "l"(p), "f"(v) : "memory");
}
__device__ __forceinline__ float load_acquire_gpu(const float* p) {
    float v;
    asm volatile("ld.global.acquire.gpu.f32 %0, [%1];" : "=f"(v) : "l"(p) : "memory");
    return v;
}

__global__ __launch_bounds__(BLOCK1) void center_loss_stage1(
    const float* __restrict__ features,
    const int*   __restrict__ labels,
    const float* __restrict__ centers)
{
    const int lane   = threadIdx.x & 31;
    const int wid    = threadIdx.x >> 5;
    const int warp_g = (blockIdx.x * BLOCK1 + threadIdx.x) >> 5;

    float acc = 0.0f;

    // Pair of rows per iteration: row0 = warp_g + k*2*NWARPS, row1 = row0 + NWARPS.
    int row0 = warp_g;
    int row1 = row0 + NWARPS;
    int lbl0 = (row0 < BATCH) ? __ldcs(labels + row0) : 0;
    int lbl1 = (row1 < BATCH) ? __ldcs(labels + row1) : 0;

    while (row0 < BATCH) {
        const int nrow0 = row0 + 2 * NWARPS;
        const int nrow1 = row1 + 2 * NWARPS;
        // prefetch next pair's labels — keeps label->center chain off critical path
        const int nlbl0 = (nrow0 < BATCH) ? __ldcs(labels + nrow0) : 0;
        const int nlbl1 = (nrow1 < BATCH) ? __ldcs(labels + nrow1) : 0;

        const bool have1 = (row1 < BATCH);

        const float4* __restrict__ f0p =
            reinterpret_cast<const float4*>(features + (size_t)row0 * FEAT_DIM);
        const float4* __restrict__ c0p =
            reinterpret_cast<const float4*>(centers + (size_t)lbl0 * FEAT_DIM);
        const float4* __restrict__ f1p =
            reinterpret_cast<const float4*>(features + (size_t)(have1 ? row1 : row0) * FEAT_DIM);
        const float4* __restrict__ c1p =
            reinterpret_cast<const float4*>(centers + (size_t)lbl1 * FEAT_DIM);

        // Issue all 8 independent 16B loads up front (MLP=8 per lane).
        float4 fa = __ldcs(f0p + lane);
        float4 fb = __ldcs(f0p + lane + 32);
        float4 ca = __ldg (c0p + lane);
        float4 cb = __ldg (c0p + lane + 32);
        float4 fc = __ldcs(f1p + lane);
        float4 fd = __ldcs(f1p + lane + 32);
        float4 cc = __ldg (c1p + lane);
        float4 cd = __ldg (c1p + lane + 32);

        float d;
        d = fa.x - ca.x; acc = fmaf(d, d, acc);
        d = fa.y - ca.y; acc = fmaf(d, d, acc);
        d = fa.z - ca.z; acc = fmaf(d, d, acc);
        d = fa.w - ca.w; acc = fmaf(d, d, acc);
        d = fb.x - cb.x; acc = fmaf(d, d, acc);
        d = fb.y - cb.y; acc = fmaf(d, d, acc);
        d = fb.z - cb.z; acc = fmaf(d, d, acc);
        d = fb.w - cb.w; acc = fmaf(d, d, acc);

        if (have1) {
            d = fc.x - cc.x; acc = fmaf(d, d, acc);
            d = fc.y - cc.y; acc = fmaf(d, d, acc);
            d = fc.z - cc.z; acc = fmaf(d, d, acc);
            d = fc.w - cc.w; acc = fmaf(d, d, acc);
            d = fd.x - cd.x; acc = fmaf(d, d, acc);
            d = fd.y - cd.y; acc = fmaf(d, d, acc);
            d = fd.z - cd.z; acc = fmaf(d, d, acc);
            d = fd.w - cd.w; acc = fmaf(d, d, acc);
        }

        row0 = nrow0; row1 = nrow1;
        lbl0 = nlbl0; lbl1 = nlbl1;
    }

    // warp reduce
    #pragma unroll
    for (int o = 16; o > 0; o >>= 1)
        acc += __shfl_xor_sync(0xFFFFFFFFu, acc, o);

    __shared__ float smem[BLOCK1 / 32];
    if (lane == 0) smem[wid] = acc;
    __syncthreads();

    if (threadIdx.x == 0) {
        float v = 0.0f;
        #pragma unroll
        for (int i = 0; i < BLOCK1 / 32; i++) v += smem[i];
        // release store: visible to dependent grid, no MEMBAR/CCTL.IVALL
        store_release_gpu(&g_partials[blockIdx.x], v);
    }
    __syncthreads();

    cudaTriggerProgrammaticLaunchCompletion();
}

__global__ __launch_bounds__(256) void center_loss_stage2(float* __restrict__ out)
{
    cudaGridDependencySynchronize();

    const int tid = threadIdx.x;
    float acc = 0.0f;
    for (int i = tid; i < GRID1; i += 256)
        acc += load_acquire_gpu(&g_partials[i]);

    #pragma unroll
    for (int o = 16; o > 0; o >>= 1)
        acc += __shfl_xor_sync(0xFFFFFFFFu, acc, o);

    __shared__ float smem[8];
    if ((tid & 31) == 0) smem[tid >> 5] = acc;
    __syncthreads();

    if (tid == 0) {
        float t = 0.0f;
        #pragma unroll
        for (int i = 0; i < 8; i++) t += smem[i];
        out[0] = t * (1.0f / (float)BATCH);   // LAMBDA_C = 1.0
    }
}

extern "C" void kernel_launch(void* const* d_in, const int* in_sizes, int n_in,
                              void* d_out, int out_size)
{
    const float* features = (const float*)d_in[0];
    const int*   labels   = (const int*)  d_in[1];
    const float* centers  = (const float*)d_in[2];
    float*       out      = (float*)d_out;

    center_loss_stage1<<<GRID1, BLOCK1>>>(features, labels, centers);

    cudaLaunchAttribute attrs[1];
    attrs[0].id = cudaLaunchAttributeProgrammaticStreamSerialization;
    attrs[0].val.programmaticStreamSerializationAllowed = 1;

    cudaLaunchConfig_t cfg = {};
    cfg.gridDim  = dim3(1, 1, 1);
    cfg.blockDim = dim3(256, 1, 1);
    cfg.dynamicSmemBytes = 0;
    cfg.stream   = 0;
    cfg.attrs    = attrs;
    cfg.numAttrs = 1;

    cudaLaunchKernelEx(&cfg, center_loss_stage2, out);
}

// round 7
// speedup vs baseline: 1.2239x; 1.2239x over previous
#include <cuda_runtime.h>
#include <cuda_bf16.h>

// CenterLoss: loss = mean_b sum_d (features[b,d] - centers[labels[b],d])^2
// B=65536, D=256, C=100000. HBM-bound gather + reduction.
// R5 configuration (proven 16.86us) + locked occupancy + vectorized stage2.
// Stage1: 1 row/warp-iter, __ldcs streaming features (protect L2 center reuse),
//         label software-pipelined, __threadfence + plain partial store.
// Stage2: PDL-overlapped, float4 loads of partials.

#define BATCH    65536
#define FEAT_DIM 256
#define GRID1    1184          // 8 CTAs/SM * 148 SMs
#define BLOCK1   256           // 8 warps per CTA
#define NWARPS   ((GRID1 * BLOCK1) >> 5)   // 9472

__device__ __align__(16) float g_partials[GRID1];

__global__ __launch_bounds__(BLOCK1, 8) void center_loss_stage1(
    const float* __restrict__ features,
    const int*   __restrict__ labels,
    const float* __restrict__ centers)
{
    const int lane   = threadIdx.x & 31;
    const int wid    = threadIdx.x >> 5;
    const int warp_g = (blockIdx.x * BLOCK1 + threadIdx.x) >> 5;

    float acc = 0.0f;

    int row = warp_g;
    int lbl = (row < BATCH) ? __ldcs(labels + row) : 0;   // pipelined label

    for (; row < BATCH; ) {
        const int next_row = row + NWARPS;
        // prefetch next label early — breaks label->address->load serial chain
        const int next_lbl = (next_row < BATCH) ? __ldcs(labels + next_row) : 0;

        const float4* __restrict__ f =
            reinterpret_cast<const float4*>(features + (size_t)row * FEAT_DIM);
        const float4* __restrict__ c =
            reinterpret_cast<const float4*>(centers + (size_t)lbl * FEAT_DIM);

        // 256 floats per row = 64 float4; 32 lanes * 2 float4 each.
        // features: streaming (no reuse — keep them out of L2's way)
        float4 f0 = __ldcs(f + lane);
        float4 f1 = __ldcs(f + lane + 32);
        // centers: default caching (repeat labels hit L2)
        float4 c0 = __ldg(c + lane);
        float4 c1 = __ldg(c + lane + 32);

        float d;
        d = f0.x - c0.x; acc = fmaf(d, d, acc);
        d = f0.y - c0.y; acc = fmaf(d, d, acc);
        d = f0.z - c0.z; acc = fmaf(d, d, acc);
        d = f0.w - c0.w; acc = fmaf(d, d, acc);
        d = f1.x - c1.x; acc = fmaf(d, d, acc);
        d = f1.y - c1.y; acc = fmaf(d, d, acc);
        d = f1.z - c1.z; acc = fmaf(d, d, acc);
        d = f1.w - c1.w; acc = fmaf(d, d, acc);

        row = next_row;
        lbl = next_lbl;
    }

    // warp reduce
    #pragma unroll
    for (int o = 16; o > 0; o >>= 1)
        acc += __shfl_xor_sync(0xFFFFFFFFu, acc, o);

    __shared__ float smem[BLOCK1 / 32];
    if (lane == 0) smem[wid] = acc;
    __syncthreads();

    if (threadIdx.x == 0) {
        float v = 0.0f;
        #pragma unroll
        for (int i = 0; i < BLOCK1 / 32; i++) v += smem[i];
        g_partials[blockIdx.x] = v;
        __threadfence();   // partial visible before dependent grid reads it
    }
    __syncthreads();

    cudaTriggerProgrammaticLaunchCompletion();
}

__global__ __launch_bounds__(1024) void center_loss_stage2(float* __restrict__ out)
{
    cudaGridDependencySynchronize();

    const int tid = threadIdx.x;
    // 1184 partials = 296 float4, one per thread (tid < 296).
    float acc = 0.0f;
    if (tid < GRID1 / 4) {
        float4 p = reinterpret_cast<const float4*>(g_partials)[tid];
        acc = (p.x + p.y) + (p.z + p.w);
    }

    #pragma unroll
    for (int o = 16; o > 0; o >>= 1)
        acc += __shfl_xor_sync(0xFFFFFFFFu, acc, o);

    __shared__ float smem[32];
    if ((tid & 31) == 0) smem[tid >> 5] = acc;
    __syncthreads();

    if (tid < 32) {
        float v = smem[tid];
        #pragma unroll
        for (int o = 16; o > 0; o >>= 1)
            v += __shfl_xor_sync(0xFFFFFFFFu, v, o);
        if (tid == 0)
            out[0] = v * (1.0f / (float)BATCH);   // LAMBDA_C = 1.0
    }
}

extern "C" void kernel_launch(void* const* d_in, const int* in_sizes, int n_in,
                              void* d_out, int out_size)
{
    const float* features = (const float*)d_in[0];
    const int*   labels   = (const int*)  d_in[1];
    const float* centers  = (const float*)d_in[2];
    float*       out      = (float*)d_out;

    center_loss_stage1<<<GRID1, BLOCK1>>>(features, labels, centers);

    cudaLaunchAttribute attrs[1];
    attrs[0].id = cudaLaunchAttributeProgrammaticStreamSerialization;
    attrs[0].val.programmaticStreamSerializationAllowed = 1;

    cudaLaunchConfig_t cfg = {};
    cfg.gridDim  = dim3(1, 1, 1);
    cfg.blockDim = dim3(1024, 1, 1);
    cfg.dynamicSmemBytes = 0;
    cfg.stream   = 0;
    cfg.attrs    = attrs;
    cfg.numAttrs = 1;

    cudaLaunchKernelEx(&cfg, center_loss_stage2, out);
}